// round 5
// baseline (speedup 1.0000x reference)
#include <cuda_runtime.h>
#include <cstdint>

#define MAX_N 50000
#define MAX_E 800000
#define MAX_B 64
#define D 128

// ---------------- scratch (static device globals; no allocation) -------------
__device__ float g_xw[MAX_N * D];      // xw1 (GEMM1 out), gather source for fusedA
__device__ float g_xw2[MAX_N * D];     // xw2 (fusedA out), gather source for fusedB
__device__ int   g_cnt[MAX_N];
__device__ int   g_row_start[MAX_N + 1];
__device__ int   g_cursor[MAX_N];
__device__ int   g_perm_src[MAX_E];
__device__ float g_perm_w[MAX_E];
__device__ int   g_root_of[MAX_N];     // graph id + 1 if node is a root, else 0
__device__ float g_rooth[MAX_B * D];   // raw h1 rows at roots
__device__ float g_r2[MAX_B * D];      // leaky(x0[root]) @ W2[128:]
__device__ float g_r3[MAX_B * D];      // h1[root] @ Wl[128:]

__device__ __forceinline__ float leaky(float x) { return x > 0.f ? x : 0.01f * x; }
__device__ __forceinline__ float to_tf32(float x) {
    float r; asm("cvt.rna.tf32.f32 %0, %1;" : "=f"(r) : "f"(x)); return r;
}
__device__ __forceinline__ void mma_tf32(float& c0, float& c1, float& c2, float& c3,
                                         float a0, float a1, float a2, float a3,
                                         float b0, float b1) {
    asm volatile(
        "mma.sync.aligned.m16n8k8.row.col.f32.tf32.tf32.f32 "
        "{%0,%1,%2,%3}, {%4,%5,%6,%7}, {%8,%9}, {%0,%1,%2,%3};"
        : "+f"(c0), "+f"(c1), "+f"(c2), "+f"(c3)
        : "r"(__float_as_uint(a0)), "r"(__float_as_uint(a1)),
          "r"(__float_as_uint(a2)), "r"(__float_as_uint(a3)),
          "r"(__float_as_uint(b0)), "r"(__float_as_uint(b1)));
}

// ---------------- CSR build --------------------------------------------------
__global__ void k_hist(const int* __restrict__ dst, int E) {
    int i = blockIdx.x * blockDim.x + threadIdx.x;
    if (i < E) atomicAdd(&g_cnt[dst[i]], 1);
}

__global__ void k_scan2(int n) {
    extern __shared__ int sc[];
    __shared__ int ssum[1024];
    const int t = threadIdx.x;
    for (int i = t; i < n; i += 1024) sc[i] = g_cnt[i];
    __syncthreads();
    const int CH = (n + 1023) >> 10;
    const int base = t * CH;
    int s = 0;
    for (int i = 0; i < CH; i++) { int idx = base + i; if (idx < n) s += sc[idx]; }
    ssum[t] = s;
    __syncthreads();
    for (int off = 1; off < 1024; off <<= 1) {
        int v = (t >= off) ? ssum[t - off] : 0;
        __syncthreads(); ssum[t] += v; __syncthreads();
    }
    int pre = (t == 0) ? 0 : ssum[t - 1];
    for (int i = 0; i < CH; i++) {
        int idx = base + i;
        if (idx < n) { int c = sc[idx]; sc[idx] = pre; pre += c; }
    }
    __syncthreads();
    if (t == 0) sc[n] = ssum[1023];
    __syncthreads();
    for (int i = t; i <= n; i += 1024) {
        int v = sc[i];
        g_row_start[i] = v;
        if (i < n) g_cursor[i] = v;
    }
}

__global__ void k_scatter(const int* __restrict__ src, const int* __restrict__ dst,
                          const float* __restrict__ w, int E) {
    int i = blockIdx.x * blockDim.x + threadIdx.x;
    if (i < E) {
        int d   = dst[i];
        int pos = atomicAdd(&g_cursor[d], 1);
        g_perm_src[pos] = src[i];
        g_perm_w[pos]   = w[i];
    }
}

__global__ void k_mark_roots(const int* __restrict__ root_idx, int B) {
    int g = threadIdx.x;
    if (g < B) g_root_of[root_idx[g]] = g + 1;
}

// ---------------- root projections: dst[g] = op(src[row_g]) @ W[128:256] -----
__global__ void k_rootp(const float* __restrict__ src, const float* __restrict__ Wfull,
                        float* __restrict__ dst, const int* __restrict__ root_idx,
                        int do_leaky) {
    int g = blockIdx.x, c = threadIdx.x;
    __shared__ float xv[128];
    int row = root_idx ? root_idx[g] : g;
    float v = src[(size_t)row * 128 + c];
    xv[c] = do_leaky ? leaky(v) : v;
    __syncthreads();
    float a = 0.f;
#pragma unroll 8
    for (int k = 0; k < 128; k++)
        a = fmaf(xv[k], Wfull[(size_t)(128 + k) * 128 + c], a);
    dst[g * 128 + c] = a;
}

// ---------------- mma.sync tf32 GEMM (standalone, GEMM1) ----------------------
#define SA 132
#define SB 136
__global__ void __launch_bounds__(256, 1)
k_mma(const float* __restrict__ A, const float* __restrict__ B,
      float* __restrict__ C, int M, int nTiles) {
    extern __shared__ float sm[];
    float* A_s = sm;
    float* B_s = sm + 128 * SA;

    const int tid    = threadIdx.x;
    const int wid    = tid >> 5;
    const int lane   = tid & 31;
    const int g      = lane >> 2;
    const int tig    = lane & 3;
    const int warp_m = wid >> 2;
    const int warp_n = wid & 3;

#pragma unroll
    for (int i = 0; i < 16; i++) {
        int idx = tid + i * 256;
        int r = idx >> 5, c4 = idx & 31;
        float4 v = ((const float4*)B)[idx];
        v.x = to_tf32(v.x); v.y = to_tf32(v.y); v.z = to_tf32(v.z); v.w = to_tf32(v.w);
        *(float4*)(B_s + r * SB + c4 * 4) = v;
    }

    for (int t = blockIdx.x; t < nTiles; t += gridDim.x) {
        const int row0 = t * 128;
        __syncthreads();
#pragma unroll
        for (int i = 0; i < 16; i++) {
            int idx = tid + i * 256;
            int r = idx >> 5, c4 = idx & 31;
            int gr = row0 + r;
            float4 v = make_float4(0.f, 0.f, 0.f, 0.f);
            if (gr < M) v = *(const float4*)(A + (size_t)gr * 128 + c4 * 4);
            v.x = to_tf32(v.x); v.y = to_tf32(v.y); v.z = to_tf32(v.z); v.w = to_tf32(v.w);
            *(float4*)(A_s + r * SA + c4 * 4) = v;
        }
        __syncthreads();

        float acc[4][4][4];
#pragma unroll
        for (int mt = 0; mt < 4; mt++)
#pragma unroll
            for (int nt = 0; nt < 4; nt++)
#pragma unroll
                for (int q = 0; q < 4; q++) acc[mt][nt][q] = 0.f;

        const float* Ab = A_s + (warp_m * 64 + g) * SA + tig;
        const float* Bb = B_s + tig * SB + warp_n * 32 + g;
#pragma unroll
        for (int ks = 0; ks < 16; ks++) {
            const int kc = ks * 8;
            float af[4][4];
#pragma unroll
            for (int mt = 0; mt < 4; mt++) {
                const float* ap = Ab + mt * 16 * SA + kc;
                af[mt][0] = ap[0];
                af[mt][1] = ap[8 * SA];
                af[mt][2] = ap[4];
                af[mt][3] = ap[8 * SA + 4];
            }
            float bf[4][2];
#pragma unroll
            for (int nt = 0; nt < 4; nt++) {
                const float* bp = Bb + kc * SB + nt * 8;
                bf[nt][0] = bp[0];
                bf[nt][1] = bp[4 * SB];
            }
#pragma unroll
            for (int mt = 0; mt < 4; mt++)
#pragma unroll
                for (int nt = 0; nt < 4; nt++)
                    mma_tf32(acc[mt][nt][0], acc[mt][nt][1], acc[mt][nt][2], acc[mt][nt][3],
                             af[mt][0], af[mt][1], af[mt][2], af[mt][3],
                             bf[nt][0], bf[nt][1]);
        }

#pragma unroll
        for (int mt = 0; mt < 4; mt++) {
            int r0 = row0 + warp_m * 64 + mt * 16 + g;
            int r1 = r0 + 8;
#pragma unroll
            for (int nt = 0; nt < 4; nt++) {
                int col = warp_n * 32 + nt * 8 + tig * 2;
                if (r0 < M) *(float2*)(C + (size_t)r0 * 128 + col) = make_float2(acc[mt][nt][0], acc[mt][nt][1]);
                if (r1 < M) *(float2*)(C + (size_t)r1 * 128 + col) = make_float2(acc[mt][nt][2], acc[mt][nt][3]);
            }
        }
    }
}

// ---------------- fused aggregate + GEMM ---------------------------------------
// Per 128-row tile: A_tile[r] = leaky( sum_e w_e * xw[src_e] + bias_agg ), then
// C_tile = A_tile @ B + epilogue.
// phase 0 (conv2): spill raw (agg+bias) rows at roots to g_rooth;
//                  epilogue C = mma + extra[batch[row]]
// phase 1 (final): epilogue C = leaky(mma + extra[batch[row]] + bias_out)
__global__ void __launch_bounds__(256, 1)
k_fused(const float* __restrict__ xw, const float* __restrict__ B,
        float* __restrict__ C, int M, int phase,
        const float* __restrict__ bias_agg,
        const float* __restrict__ extra, const int* __restrict__ batch,
        const float* __restrict__ bias_out, int nTiles) {
    extern __shared__ float sm[];
    float* A_s = sm;
    float* B_s = sm + 128 * SA;

    const int tid    = threadIdx.x;
    const int wid    = tid >> 5;
    const int lane   = tid & 31;
    const int g      = lane >> 2;
    const int tig    = lane & 3;
    const int warp_m = wid >> 2;
    const int warp_n = wid & 3;

    // stage B (weights, k x n row-major) once
#pragma unroll
    for (int i = 0; i < 16; i++) {
        int idx = tid + i * 256;
        int r = idx >> 5, c4 = idx & 31;
        float4 v = ((const float4*)B)[idx];
        v.x = to_tf32(v.x); v.y = to_tf32(v.y); v.z = to_tf32(v.z); v.w = to_tf32(v.w);
        *(float4*)(B_s + r * SB + c4 * 4) = v;
    }

    const float4 bv = *(const float4*)(bias_agg + lane * 4);

    for (int t = blockIdx.x; t < nTiles; t += gridDim.x) {
        const int row0 = t * 128;
        __syncthreads();
        // ---- aggregate 16 rows per warp directly into A_s ----
        for (int r8 = 0; r8 < 16; r8++) {
            const int r  = wid * 16 + r8;
            const int gr = row0 + r;
            float4 acc0 = make_float4(0.f, 0.f, 0.f, 0.f);
            float4 acc1 = make_float4(0.f, 0.f, 0.f, 0.f);
            if (gr < M) {
                int s = g_row_start[gr];
                int e = g_row_start[gr + 1];
                int i = s;
                for (; i + 1 < e; i += 2) {
                    int   s0 = g_perm_src[i],     s1 = g_perm_src[i + 1];
                    float w0 = g_perm_w[i],       w1 = g_perm_w[i + 1];
                    float4 v0 = *(const float4*)(xw + (size_t)s0 * D + lane * 4);
                    float4 v1 = *(const float4*)(xw + (size_t)s1 * D + lane * 4);
                    acc0.x = fmaf(w0, v0.x, acc0.x); acc0.y = fmaf(w0, v0.y, acc0.y);
                    acc0.z = fmaf(w0, v0.z, acc0.z); acc0.w = fmaf(w0, v0.w, acc0.w);
                    acc1.x = fmaf(w1, v1.x, acc1.x); acc1.y = fmaf(w1, v1.y, acc1.y);
                    acc1.z = fmaf(w1, v1.z, acc1.z); acc1.w = fmaf(w1, v1.w, acc1.w);
                }
                if (i < e) {
                    int   s0 = g_perm_src[i];
                    float w0 = g_perm_w[i];
                    float4 v0 = *(const float4*)(xw + (size_t)s0 * D + lane * 4);
                    acc0.x = fmaf(w0, v0.x, acc0.x); acc0.y = fmaf(w0, v0.y, acc0.y);
                    acc0.z = fmaf(w0, v0.z, acc0.z); acc0.w = fmaf(w0, v0.w, acc0.w);
                }
                acc0.x += acc1.x + bv.x; acc0.y += acc1.y + bv.y;
                acc0.z += acc1.z + bv.z; acc0.w += acc1.w + bv.w;
                if (phase == 0) {
                    int rid = g_root_of[gr];
                    if (rid) *(float4*)(g_rooth + (size_t)(rid - 1) * D + lane * 4) = acc0;
                }
                acc0.x = to_tf32(leaky(acc0.x)); acc0.y = to_tf32(leaky(acc0.y));
                acc0.z = to_tf32(leaky(acc0.z)); acc0.w = to_tf32(leaky(acc0.w));
            }
            *(float4*)(A_s + r * SA + lane * 4) = acc0;
        }
        __syncthreads();

        // ---- MMA mainloop ----
        float acc[4][4][4];
#pragma unroll
        for (int mt = 0; mt < 4; mt++)
#pragma unroll
            for (int nt = 0; nt < 4; nt++)
#pragma unroll
                for (int q = 0; q < 4; q++) acc[mt][nt][q] = 0.f;

        const float* Ab = A_s + (warp_m * 64 + g) * SA + tig;
        const float* Bb = B_s + tig * SB + warp_n * 32 + g;
#pragma unroll
        for (int ks = 0; ks < 16; ks++) {
            const int kc = ks * 8;
            float af[4][4];
#pragma unroll
            for (int mt = 0; mt < 4; mt++) {
                const float* ap = Ab + mt * 16 * SA + kc;
                af[mt][0] = ap[0];
                af[mt][1] = ap[8 * SA];
                af[mt][2] = ap[4];
                af[mt][3] = ap[8 * SA + 4];
            }
            float bf[4][2];
#pragma unroll
            for (int nt = 0; nt < 4; nt++) {
                const float* bp = Bb + kc * SB + nt * 8;
                bf[nt][0] = bp[0];
                bf[nt][1] = bp[4 * SB];
            }
#pragma unroll
            for (int mt = 0; mt < 4; mt++)
#pragma unroll
                for (int nt = 0; nt < 4; nt++)
                    mma_tf32(acc[mt][nt][0], acc[mt][nt][1], acc[mt][nt][2], acc[mt][nt][3],
                             af[mt][0], af[mt][1], af[mt][2], af[mt][3],
                             bf[nt][0], bf[nt][1]);
        }

        // ---- epilogue ----
#pragma unroll
        for (int mt = 0; mt < 4; mt++) {
            int r0 = row0 + warp_m * 64 + mt * 16 + g;
            int r1 = r0 + 8;
            const float* e0 = (r0 < M) ? (extra + (size_t)batch[r0] * 128) : nullptr;
            const float* e1 = (r1 < M) ? (extra + (size_t)batch[r1] * 128) : nullptr;
#pragma unroll
            for (int nt = 0; nt < 4; nt++) {
                int col = warp_n * 32 + nt * 8 + tig * 2;
                float o0 = acc[mt][nt][0], o1 = acc[mt][nt][1];
                float o2 = acc[mt][nt][2], o3 = acc[mt][nt][3];
                if (phase == 0) {
                    if (e0) { o0 += e0[col]; o1 += e0[col + 1]; }
                    if (e1) { o2 += e1[col]; o3 += e1[col + 1]; }
                } else {
                    float bc0 = bias_out[col], bc1 = bias_out[col + 1];
                    if (e0) { o0 = leaky(o0 + e0[col] + bc0); o1 = leaky(o1 + e0[col + 1] + bc1); }
                    if (e1) { o2 = leaky(o2 + e1[col] + bc0); o3 = leaky(o3 + e1[col + 1] + bc1); }
                }
                if (r0 < M) *(float2*)(C + (size_t)r0 * 128 + col) = make_float2(o0, o1);
                if (r1 < M) *(float2*)(C + (size_t)r1 * 128 + col) = make_float2(o2, o3);
            }
        }
    }
}

// ---------------- launch ------------------------------------------------------
extern "C" void kernel_launch(void* const* d_in, const int* in_sizes, int n_in,
                              void* d_out, int out_size) {
    const float* features = (const float*)d_in[0];
    const float* values   = (const float*)d_in[1];
    const float* W1       = (const float*)d_in[2];
    const float* b1       = (const float*)d_in[3];
    const float* W2       = (const float*)d_in[4];
    const float* b2       = (const float*)d_in[5];
    const float* Wl       = (const float*)d_in[6];
    const float* bl       = (const float*)d_in[7];
    const int*   adjs     = (const int*)d_in[8];
    const int*   root_idx = (const int*)d_in[9];
    const int*   batch    = (const int*)d_in[12];
    float*       out      = (float*)d_out;

    const int N = in_sizes[0] / D;
    const int E = in_sizes[1];
    const int B = in_sizes[9];
    const int* src = adjs;
    const int* dst = adjs + E;

    float *p_xw, *p_xw2, *p_r2, *p_r3, *p_rooth;
    int   *p_cnt, *p_root_of;
    cudaGetSymbolAddress((void**)&p_xw, g_xw);
    cudaGetSymbolAddress((void**)&p_xw2, g_xw2);
    cudaGetSymbolAddress((void**)&p_r2, g_r2);
    cudaGetSymbolAddress((void**)&p_r3, g_r3);
    cudaGetSymbolAddress((void**)&p_rooth, g_rooth);
    cudaGetSymbolAddress((void**)&p_cnt, g_cnt);
    cudaGetSymbolAddress((void**)&p_root_of, g_root_of);

    static cudaStream_t s_side = nullptr;
    static cudaEvent_t  ev_fork = nullptr, ev_join = nullptr;
    if (s_side == nullptr) {
        cudaStreamCreateWithFlags(&s_side, cudaStreamNonBlocking);
        cudaEventCreateWithFlags(&ev_fork, cudaEventDisableTiming);
        cudaEventCreateWithFlags(&ev_join, cudaEventDisableTiming);
        cudaFuncSetAttribute(k_scan2, cudaFuncAttributeMaxDynamicSharedMemorySize, 220 * 1024);
        cudaFuncSetAttribute(k_mma, cudaFuncAttributeMaxDynamicSharedMemorySize, 140 * 1024);
        cudaFuncSetAttribute(k_fused, cudaFuncAttributeMaxDynamicSharedMemorySize, 140 * 1024);
    }

    const size_t scan_smem = (size_t)(N + 1) * sizeof(int);
    const size_t mma_smem  = (size_t)(128 * SA + 128 * SB) * sizeof(float);
    const int nTiles  = (N + 127) / 128;
    const int mmaGrid = nTiles < 148 ? nTiles : 148;

    // ---- fork: CSR + roots metadata + r2 on side stream, overlapped with GEMM1 ----
    cudaEventRecord(ev_fork, 0);
    cudaStreamWaitEvent(s_side, ev_fork, 0);
    cudaMemsetAsync(p_cnt, 0, (size_t)N * sizeof(int), s_side);
    cudaMemsetAsync(p_root_of, 0, (size_t)N * sizeof(int), s_side);
    k_hist<<<(E + 255) / 256, 256, 0, s_side>>>(dst, E);
    k_scan2<<<1, 1024, scan_smem, s_side>>>(N);
    k_scatter<<<(E + 255) / 256, 256, 0, s_side>>>(src, dst, values, E);
    k_mark_roots<<<1, 64, 0, s_side>>>(root_idx, B);
    k_rootp<<<B, 128, 0, s_side>>>(features, W2, p_r2, root_idx, 1);
    cudaEventRecord(ev_join, s_side);

    // GEMM1: xw1 = features @ W1 (main stream, independent of CSR)
    k_mma<<<mmaGrid, 256, mma_smem>>>(features, W1, p_xw, N, nTiles);

    // ---- join ----
    cudaStreamWaitEvent(0, ev_join, 0);

    // fused conv1-agg + conv2-GEMM: xw2 = leaky(agg(xw1)+b1) @ W2_top + r2[batch]
    k_fused<<<mmaGrid, 256, mma_smem>>>(p_xw, W2, p_xw2, N, 0, b1, p_r2, batch, nullptr, nTiles);

    // r3 = h1[root] @ Wl_bot (root h1 rows spilled by fusedA)
    k_rootp<<<B, 128>>>(p_rooth, Wl, p_r3, nullptr, 0);

    // fused conv2-agg + final GEMM: out = leaky( leaky(agg(xw2)+b2) @ Wl_top + r3[batch] + bl )
    k_fused<<<mmaGrid, 256, mma_smem>>>(p_xw2, Wl, out, N, 1, b2, p_r3, batch, bl, nTiles);
}

// round 6
// speedup vs baseline: 1.5661x; 1.5661x over previous
#include <cuda_runtime.h>
#include <cuda_fp16.h>
#include <cstdint>

#define MAX_N 50000
#define MAX_E 800000
#define MAX_B 64
#define D 128

// ---------------- scratch (static device globals; no allocation) -------------
__device__ __half g_xh1[MAX_N * D];    // GEMM1 out (fp16), gather source for agg1
__device__ __half g_xh2[MAX_N * D];    // GEMM2 out (fp16), gather source for agg2
__device__ float  g_h1[MAX_N * D];     // raw conv1 output (fp32)
__device__ float  g_a2[MAX_N * D];     // leaky(conv2 output) (fp32)
__device__ int    g_cnt[MAX_N];
__device__ int    g_row_start[MAX_N + 1];
__device__ int    g_cursor[MAX_N];
__device__ int2   g_perm[MAX_E];       // (src, w_bits) packed
__device__ float  g_r2[MAX_B * D];
__device__ float  g_r3[MAX_B * D];

__device__ __forceinline__ float leaky(float x) { return x > 0.f ? x : 0.01f * x; }
__device__ __forceinline__ float to_tf32(float x) {
    float r; asm("cvt.rna.tf32.f32 %0, %1;" : "=f"(r) : "f"(x)); return r;
}
__device__ __forceinline__ void mma_tf32(float& c0, float& c1, float& c2, float& c3,
                                         float a0, float a1, float a2, float a3,
                                         float b0, float b1) {
    asm volatile(
        "mma.sync.aligned.m16n8k8.row.col.f32.tf32.tf32.f32 "
        "{%0,%1,%2,%3}, {%4,%5,%6,%7}, {%8,%9}, {%0,%1,%2,%3};"
        : "+f"(c0), "+f"(c1), "+f"(c2), "+f"(c3)
        : "r"(__float_as_uint(a0)), "r"(__float_as_uint(a1)),
          "r"(__float_as_uint(a2)), "r"(__float_as_uint(a3)),
          "r"(__float_as_uint(b0)), "r"(__float_as_uint(b1)));
}

// ---------------- CSR build --------------------------------------------------
__global__ void k_hist(const int* __restrict__ dst, int E) {
    int i = blockIdx.x * blockDim.x + threadIdx.x;
    if (i < E) atomicAdd(&g_cnt[dst[i]], 1);
}

__global__ void k_scan2(int n) {
    extern __shared__ int sc[];
    __shared__ int ssum[1024];
    const int t = threadIdx.x;
    for (int i = t; i < n; i += 1024) sc[i] = g_cnt[i];
    __syncthreads();
    const int CH = (n + 1023) >> 10;
    const int base = t * CH;
    int s = 0;
    for (int i = 0; i < CH; i++) { int idx = base + i; if (idx < n) s += sc[idx]; }
    ssum[t] = s;
    __syncthreads();
    for (int off = 1; off < 1024; off <<= 1) {
        int v = (t >= off) ? ssum[t - off] : 0;
        __syncthreads(); ssum[t] += v; __syncthreads();
    }
    int pre = (t == 0) ? 0 : ssum[t - 1];
    for (int i = 0; i < CH; i++) {
        int idx = base + i;
        if (idx < n) { int c = sc[idx]; sc[idx] = pre; pre += c; }
    }
    __syncthreads();
    if (t == 0) sc[n] = ssum[1023];
    __syncthreads();
    for (int i = t; i <= n; i += 1024) {
        int v = sc[i];
        g_row_start[i] = v;
        if (i < n) g_cursor[i] = v;
    }
}

__global__ void k_scatter(const int* __restrict__ src, const int* __restrict__ dst,
                          const float* __restrict__ w, int E) {
    int i = blockIdx.x * blockDim.x + threadIdx.x;
    if (i < E) {
        int d   = dst[i];
        int pos = atomicAdd(&g_cursor[d], 1);
        g_perm[pos] = make_int2(src[i], __float_as_int(w[i]));
    }
}

// ---------------- root projections: dst[g] = op(src[root_g]) @ W[128:256] -----
__global__ void k_rootp(const float* __restrict__ src, const float* __restrict__ Wfull,
                        float* __restrict__ dst, const int* __restrict__ root_idx,
                        int do_leaky) {
    int g = blockIdx.x, c = threadIdx.x;
    __shared__ float xv[128];
    int row = root_idx[g];
    float v = src[(size_t)row * 128 + c];
    xv[c] = do_leaky ? leaky(v) : v;
    __syncthreads();
    float a = 0.f;
#pragma unroll 8
    for (int k = 0; k < 128; k++)
        a = fmaf(xv[k], Wfull[(size_t)(128 + k) * 128 + c], a);
    dst[g * 128 + c] = a;
}

// ---------------- mma.sync tf32 GEMM ------------------------------------------
// C[M,128] = op(A)[M,128] @ B[128,128]  (B = weight, k x n row-major)
// MODE 0: plain, OUT=half                               (GEMM1)
// MODE 1: A->leaky(A), C += extra[batch], OUT=half      (GEMM2)
// MODE 2: C = leaky(C + extra[batch] + bias), OUT=float (GEMM3)
#define SA 132
#define SB 136
template <int MODE, typename OUT_T>
__global__ void __launch_bounds__(256, 1)
k_mma(const float* __restrict__ A, const float* __restrict__ B,
      OUT_T* __restrict__ C, int M,
      const float* __restrict__ extra, const int* __restrict__ batch,
      const float* __restrict__ bias, int nTiles) {
    extern __shared__ float sm[];
    float* A_s = sm;
    float* B_s = sm + 128 * SA;

    const int tid    = threadIdx.x;
    const int wid    = tid >> 5;
    const int lane   = tid & 31;
    const int g      = lane >> 2;
    const int tig    = lane & 3;
    const int warp_m = wid >> 2;
    const int warp_n = wid & 3;

#pragma unroll
    for (int i = 0; i < 16; i++) {
        int idx = tid + i * 256;
        int r = idx >> 5, c4 = idx & 31;
        float4 v = ((const float4*)B)[idx];
        v.x = to_tf32(v.x); v.y = to_tf32(v.y); v.z = to_tf32(v.z); v.w = to_tf32(v.w);
        *(float4*)(B_s + r * SB + c4 * 4) = v;
    }

    for (int t = blockIdx.x; t < nTiles; t += gridDim.x) {
        const int row0 = t * 128;
        __syncthreads();
#pragma unroll
        for (int i = 0; i < 16; i++) {
            int idx = tid + i * 256;
            int r = idx >> 5, c4 = idx & 31;
            int gr = row0 + r;
            float4 v = make_float4(0.f, 0.f, 0.f, 0.f);
            if (gr < M) {
                v = *(const float4*)(A + (size_t)gr * 128 + c4 * 4);
                if (MODE == 1) { v.x = leaky(v.x); v.y = leaky(v.y); v.z = leaky(v.z); v.w = leaky(v.w); }
            }
            v.x = to_tf32(v.x); v.y = to_tf32(v.y); v.z = to_tf32(v.z); v.w = to_tf32(v.w);
            *(float4*)(A_s + r * SA + c4 * 4) = v;
        }
        __syncthreads();

        float acc[4][4][4];
#pragma unroll
        for (int mt = 0; mt < 4; mt++)
#pragma unroll
            for (int nt = 0; nt < 4; nt++)
#pragma unroll
                for (int q = 0; q < 4; q++) acc[mt][nt][q] = 0.f;

        const float* Ab = A_s + (warp_m * 64 + g) * SA + tig;
        const float* Bb = B_s + tig * SB + warp_n * 32 + g;
#pragma unroll
        for (int ks = 0; ks < 16; ks++) {
            const int kc = ks * 8;
            float af[4][4];
#pragma unroll
            for (int mt = 0; mt < 4; mt++) {
                const float* ap = Ab + mt * 16 * SA + kc;
                af[mt][0] = ap[0];
                af[mt][1] = ap[8 * SA];
                af[mt][2] = ap[4];
                af[mt][3] = ap[8 * SA + 4];
            }
            float bf[4][2];
#pragma unroll
            for (int nt = 0; nt < 4; nt++) {
                const float* bp = Bb + kc * SB + nt * 8;
                bf[nt][0] = bp[0];
                bf[nt][1] = bp[4 * SB];
            }
#pragma unroll
            for (int mt = 0; mt < 4; mt++)
#pragma unroll
                for (int nt = 0; nt < 4; nt++)
                    mma_tf32(acc[mt][nt][0], acc[mt][nt][1], acc[mt][nt][2], acc[mt][nt][3],
                             af[mt][0], af[mt][1], af[mt][2], af[mt][3],
                             bf[nt][0], bf[nt][1]);
        }

        // ---- epilogue ----
#pragma unroll
        for (int mt = 0; mt < 4; mt++) {
            int r0 = row0 + warp_m * 64 + mt * 16 + g;
            int r1 = r0 + 8;
            const float* e0 = nullptr; const float* e1 = nullptr;
            if (MODE != 0) {
                if (r0 < M) e0 = extra + (size_t)batch[r0] * 128;
                if (r1 < M) e1 = extra + (size_t)batch[r1] * 128;
            }
#pragma unroll
            for (int nt = 0; nt < 4; nt++) {
                int col = warp_n * 32 + nt * 8 + tig * 2;
                float o0 = acc[mt][nt][0], o1 = acc[mt][nt][1];
                float o2 = acc[mt][nt][2], o3 = acc[mt][nt][3];
                if (MODE == 1) {
                    if (e0) { o0 += e0[col]; o1 += e0[col + 1]; }
                    if (e1) { o2 += e1[col]; o3 += e1[col + 1]; }
                } else if (MODE == 2) {
                    float bc0 = bias[col], bc1 = bias[col + 1];
                    if (e0) { o0 = leaky(o0 + e0[col] + bc0); o1 = leaky(o1 + e0[col + 1] + bc1); }
                    if (e1) { o2 = leaky(o2 + e1[col] + bc0); o3 = leaky(o3 + e1[col + 1] + bc1); }
                }
                if (sizeof(OUT_T) == 2) {
                    __half2* Ch = (__half2*)C;
                    if (r0 < M) Ch[((size_t)r0 * 128 + col) >> 1] = __floats2half2_rn(o0, o1);
                    if (r1 < M) Ch[((size_t)r1 * 128 + col) >> 1] = __floats2half2_rn(o2, o3);
                } else {
                    float* Cf = (float*)C;
                    if (r0 < M) *(float2*)(Cf + (size_t)r0 * 128 + col) = make_float2(o0, o1);
                    if (r1 < M) *(float2*)(Cf + (size_t)r1 * 128 + col) = make_float2(o2, o3);
                }
            }
        }
    }
}

// ---------------- aggregation (fp16 gather): one warp per dst node -------------
__global__ void k_agg_h(const __half* __restrict__ xw, float* __restrict__ out,
                        const float* __restrict__ bias, int act, int n) {
    int gw   = (blockIdx.x * blockDim.x + threadIdx.x) >> 5;
    int lane = threadIdx.x & 31;
    if (gw >= n) return;
    int s = g_row_start[gw];
    int e = g_row_start[gw + 1];
    float4 acc0 = make_float4(0.f, 0.f, 0.f, 0.f);
    float4 acc1 = make_float4(0.f, 0.f, 0.f, 0.f);
    int i = s;
    for (; i + 1 < e; i += 2) {
        int2 e0 = g_perm[i];
        int2 e1 = g_perm[i + 1];
        float w0 = __int_as_float(e0.y);
        float w1 = __int_as_float(e1.y);
        uint2 u0 = *(const uint2*)((const __half2*)(xw + (size_t)e0.x * D) + lane * 2);
        uint2 u1 = *(const uint2*)((const __half2*)(xw + (size_t)e1.x * D) + lane * 2);
        float2 a = __half22float2(*(__half2*)&u0.x);
        float2 b = __half22float2(*(__half2*)&u0.y);
        float2 c = __half22float2(*(__half2*)&u1.x);
        float2 d = __half22float2(*(__half2*)&u1.y);
        acc0.x = fmaf(w0, a.x, acc0.x); acc0.y = fmaf(w0, a.y, acc0.y);
        acc0.z = fmaf(w0, b.x, acc0.z); acc0.w = fmaf(w0, b.y, acc0.w);
        acc1.x = fmaf(w1, c.x, acc1.x); acc1.y = fmaf(w1, c.y, acc1.y);
        acc1.z = fmaf(w1, d.x, acc1.z); acc1.w = fmaf(w1, d.y, acc1.w);
    }
    if (i < e) {
        int2 e0 = g_perm[i];
        float w0 = __int_as_float(e0.y);
        uint2 u0 = *(const uint2*)((const __half2*)(xw + (size_t)e0.x * D) + lane * 2);
        float2 a = __half22float2(*(__half2*)&u0.x);
        float2 b = __half22float2(*(__half2*)&u0.y);
        acc0.x = fmaf(w0, a.x, acc0.x); acc0.y = fmaf(w0, a.y, acc0.y);
        acc0.z = fmaf(w0, b.x, acc0.z); acc0.w = fmaf(w0, b.y, acc0.w);
    }
    float4 bv = *(const float4*)(bias + lane * 4);
    float4 acc = make_float4(acc0.x + acc1.x + bv.x, acc0.y + acc1.y + bv.y,
                             acc0.z + acc1.z + bv.z, acc0.w + acc1.w + bv.w);
    if (act) {
        acc.x = leaky(acc.x); acc.y = leaky(acc.y);
        acc.z = leaky(acc.z); acc.w = leaky(acc.w);
    }
    *(float4*)(out + (size_t)gw * D + lane * 4) = acc;
}

// ---------------- launch ------------------------------------------------------
extern "C" void kernel_launch(void* const* d_in, const int* in_sizes, int n_in,
                              void* d_out, int out_size) {
    const float* features = (const float*)d_in[0];
    const float* values   = (const float*)d_in[1];
    const float* W1       = (const float*)d_in[2];
    const float* b1       = (const float*)d_in[3];
    const float* W2       = (const float*)d_in[4];
    const float* b2       = (const float*)d_in[5];
    const float* Wl       = (const float*)d_in[6];
    const float* bl       = (const float*)d_in[7];
    const int*   adjs     = (const int*)d_in[8];
    const int*   root_idx = (const int*)d_in[9];
    const int*   batch    = (const int*)d_in[12];
    float*       out      = (float*)d_out;

    const int N = in_sizes[0] / D;
    const int E = in_sizes[1];
    const int B = in_sizes[9];
    const int* src = adjs;
    const int* dst = adjs + E;

    __half *p_xh1, *p_xh2;
    float  *p_h1, *p_a2, *p_r2, *p_r3;
    int    *p_cnt;
    cudaGetSymbolAddress((void**)&p_xh1, g_xh1);
    cudaGetSymbolAddress((void**)&p_xh2, g_xh2);
    cudaGetSymbolAddress((void**)&p_h1, g_h1);
    cudaGetSymbolAddress((void**)&p_a2, g_a2);
    cudaGetSymbolAddress((void**)&p_r2, g_r2);
    cudaGetSymbolAddress((void**)&p_r3, g_r3);
    cudaGetSymbolAddress((void**)&p_cnt, g_cnt);

    static cudaStream_t s_side = nullptr;
    static cudaEvent_t  ev_fork = nullptr, ev_join = nullptr, ev_h1 = nullptr, ev_r3 = nullptr;
    if (s_side == nullptr) {
        cudaStreamCreateWithFlags(&s_side, cudaStreamNonBlocking);
        cudaEventCreateWithFlags(&ev_fork, cudaEventDisableTiming);
        cudaEventCreateWithFlags(&ev_join, cudaEventDisableTiming);
        cudaEventCreateWithFlags(&ev_h1,   cudaEventDisableTiming);
        cudaEventCreateWithFlags(&ev_r3,   cudaEventDisableTiming);
        cudaFuncSetAttribute(k_scan2, cudaFuncAttributeMaxDynamicSharedMemorySize, 220 * 1024);
        cudaFuncSetAttribute(k_mma<0, __half>, cudaFuncAttributeMaxDynamicSharedMemorySize, 140 * 1024);
        cudaFuncSetAttribute(k_mma<1, __half>, cudaFuncAttributeMaxDynamicSharedMemorySize, 140 * 1024);
        cudaFuncSetAttribute(k_mma<2, float>,  cudaFuncAttributeMaxDynamicSharedMemorySize, 140 * 1024);
    }

    const size_t scan_smem = (size_t)(N + 1) * sizeof(int);
    const size_t mma_smem  = (size_t)(128 * SA + 128 * SB) * sizeof(float);
    const int nTiles    = (N + 127) / 128;
    const int mmaGrid   = nTiles < 148 ? nTiles : 148;
    const int aggBlocks = (N * 32 + 255) / 256;

    // ---- fork: CSR + r2 on side stream, overlapped with GEMM1 ----
    cudaEventRecord(ev_fork, 0);
    cudaStreamWaitEvent(s_side, ev_fork, 0);
    cudaMemsetAsync(p_cnt, 0, (size_t)N * sizeof(int), s_side);
    k_hist<<<(E + 255) / 256, 256, 0, s_side>>>(dst, E);
    k_scan2<<<1, 1024, scan_smem, s_side>>>(N);
    k_scatter<<<(E + 255) / 256, 256, 0, s_side>>>(src, dst, values, E);
    k_rootp<<<B, 128, 0, s_side>>>(features, W2, p_r2, root_idx, 1);
    cudaEventRecord(ev_join, s_side);

    // GEMM1: xh1 = features @ W1 (fp16 out)
    k_mma<0, __half><<<mmaGrid, 256, mma_smem>>>(features, W1, p_xh1, N,
                                                 nullptr, nullptr, nullptr, nTiles);
    cudaStreamWaitEvent(0, ev_join, 0);

    // agg1: h1 = agg(xh1) + b1 (raw fp32)
    k_agg_h<<<aggBlocks, 256>>>(p_xh1, p_h1, b1, 0, N);

    // r3 = h1[root] @ Wl_bot on side stream, overlapped with GEMM2/agg2
    cudaEventRecord(ev_h1, 0);
    cudaStreamWaitEvent(s_side, ev_h1, 0);
    k_rootp<<<B, 128, 0, s_side>>>(p_h1, Wl, p_r3, root_idx, 0);
    cudaEventRecord(ev_r3, s_side);

    // GEMM2: xh2 = leaky(h1) @ W2_top + r2[batch] (fp16 out)
    k_mma<1, __half><<<mmaGrid, 256, mma_smem>>>(p_h1, W2, p_xh2, N,
                                                 p_r2, batch, nullptr, nTiles);
    // agg2: a2 = leaky(agg(xh2) + b2)
    k_agg_h<<<aggBlocks, 256>>>(p_xh2, p_a2, b2, 1, N);

    cudaStreamWaitEvent(0, ev_r3, 0);
    // GEMM3: out = leaky(a2 @ Wl_top + r3[batch] + bl)
    k_mma<2, float><<<mmaGrid, 256, mma_smem>>>(p_a2, Wl, out, N,
                                                p_r3, batch, bl, nTiles);
}

// round 8
// speedup vs baseline: 1.6697x; 1.0662x over previous
#include <cuda_runtime.h>
#include <cuda_fp16.h>
#include <cstdint>

#define MAX_N 50000
#define MAX_E 800000
#define MAX_B 64
#define D 128

// ---------------- scratch (static device globals; no allocation) -------------
__device__ __half g_xh1[MAX_N * D];    // GEMM1 out (fp16), gather source for agg1
__device__ __half g_xh2[MAX_N * D];    // GEMM2 out (fp16), gather source for agg2
__device__ float  g_lh1[MAX_N * D];    // to_tf32(leaky(h1))  (GEMM2 A input)
__device__ float  g_la2[MAX_N * D];    // to_tf32(leaky(conv2)) (GEMM3 A input)
__device__ int    g_cnt[MAX_N];
__device__ int    g_row_start[MAX_N + 1];
__device__ int    g_cursor[MAX_N];
__device__ int2   g_perm[MAX_E];       // (src, w_bits)
__device__ float  g_r2[MAX_B * D];
__device__ float  g_r3[MAX_B * D];

__device__ __forceinline__ float leaky(float x) { return x > 0.f ? x : 0.01f * x; }
__device__ __forceinline__ float inv_leaky(float x) { return x > 0.f ? x : 100.0f * x; }
__device__ __forceinline__ float to_tf32(float x) {
    float r; asm("cvt.rna.tf32.f32 %0, %1;" : "=f"(r) : "f"(x)); return r;
}
__device__ __forceinline__ void mma_tf32(float& c0, float& c1, float& c2, float& c3,
                                         float a0, float a1, float a2, float a3,
                                         float b0, float b1) {
    asm volatile(
        "mma.sync.aligned.m16n8k8.row.col.f32.tf32.tf32.f32 "
        "{%0,%1,%2,%3}, {%4,%5,%6,%7}, {%8,%9}, {%0,%1,%2,%3};"
        : "+f"(c0), "+f"(c1), "+f"(c2), "+f"(c3)
        : "r"(__float_as_uint(a0)), "r"(__float_as_uint(a1)),
          "r"(__float_as_uint(a2)), "r"(__float_as_uint(a3)),
          "r"(__float_as_uint(b0)), "r"(__float_as_uint(b1)));
}
__device__ __forceinline__ void cp_async16(uint32_t dst, const void* src, int src_bytes) {
    asm volatile("cp.async.cg.shared.global [%0], [%1], 16, %2;"
                 :: "r"(dst), "l"(src), "r"(src_bytes) : "memory");
}
#define CP_COMMIT() asm volatile("cp.async.commit_group;" ::: "memory")
#define CP_WAIT(n)  asm volatile("cp.async.wait_group %0;" :: "n"(n) : "memory")

// ---------------- CSR build --------------------------------------------------
__global__ void k_hist(const int* __restrict__ dst, int E) {
    int i = blockIdx.x * blockDim.x + threadIdx.x;
    if (i < E) atomicAdd(&g_cnt[dst[i]], 1);
}

__global__ void k_scan2(int n) {
    extern __shared__ int sc[];
    __shared__ int ssum[1024];
    const int t = threadIdx.x;
    for (int i = t; i < n; i += 1024) sc[i] = g_cnt[i];
    __syncthreads();
    const int CH = (n + 1023) >> 10;
    const int base = t * CH;
    int s = 0;
    for (int i = 0; i < CH; i++) { int idx = base + i; if (idx < n) s += sc[idx]; }
    ssum[t] = s;
    __syncthreads();
    for (int off = 1; off < 1024; off <<= 1) {
        int v = (t >= off) ? ssum[t - off] : 0;
        __syncthreads(); ssum[t] += v; __syncthreads();
    }
    int pre = (t == 0) ? 0 : ssum[t - 1];
    for (int i = 0; i < CH; i++) {
        int idx = base + i;
        if (idx < n) { int c = sc[idx]; sc[idx] = pre; pre += c; }
    }
    __syncthreads();
    if (t == 0) sc[n] = ssum[1023];
    __syncthreads();
    for (int i = t; i <= n; i += 1024) {
        int v = sc[i];
        g_row_start[i] = v;
        if (i < n) g_cursor[i] = v;
    }
}

__global__ void k_scatter(const int* __restrict__ src, const int* __restrict__ dst,
                          const float* __restrict__ w, int E) {
    int i = blockIdx.x * blockDim.x + threadIdx.x;
    if (i < E) {
        int d   = dst[i];
        int pos = atomicAdd(&g_cursor[d], 1);
        g_perm[pos] = make_int2(src[i], __float_as_int(w[i]));
    }
}

// ---------------- root projections (split-k, 512 threads/graph) ---------------
// dst[g] = xform(src[root_g]) @ W[128:256];  xform: 0 = leaky, 1 = inv_leaky
__global__ void k_rootp2(const float* __restrict__ src, const float* __restrict__ Wfull,
                         float* __restrict__ dst, const int* __restrict__ root_idx,
                         int xform) {
    __shared__ float xv[128];
    __shared__ float part[4][128];
    const int g     = blockIdx.x;
    const int tid   = threadIdx.x;
    const int c     = tid & 127;
    const int slice = tid >> 7;
    if (tid < 128) {
        float v = src[(size_t)root_idx[g] * 128 + tid];
        xv[tid] = (xform == 0) ? leaky(v) : inv_leaky(v);
    }
    __syncthreads();
    float a = 0.f;
    const int k0 = slice * 32;
#pragma unroll 8
    for (int k = 0; k < 32; k++)
        a = fmaf(xv[k0 + k], Wfull[(size_t)(128 + k0 + k) * 128 + c], a);
    part[slice][c] = a;
    __syncthreads();
    if (tid < 128)
        dst[g * 128 + tid] = part[0][tid] + part[1][tid] + part[2][tid] + part[3][tid];
}

// ---------------- mma.sync tf32 GEMM ------------------------------------------
// C[M,128] = A[M,128] @ B[128,128]  (B = weight, k x n row-major)
// STAGE 0: register staging + cvt (A raw fp32)        — GEMM1
// STAGE 1: cp.async double-buffer (A pre-tf32-rounded) — GEMM2/3
// MODE 0: plain; MODE 1: C += extra[batch]; MODE 2: C = leaky(C+extra[batch]+bias)
#define SA 132
#define SB 136
template <int MODE, int STAGE, typename OUT_T>
__global__ void __launch_bounds__(256, 1)
k_mma(const float* __restrict__ A, const float* __restrict__ B,
      OUT_T* __restrict__ C, int M,
      const float* __restrict__ extra, const int* __restrict__ batch,
      const float* __restrict__ bias, int nTiles) {
    extern __shared__ float sm[];
    const int nAbuf = (STAGE == 1) ? 2 : 1;
    float* B_s = sm + nAbuf * 128 * SA;

    const int tid    = threadIdx.x;
    const int wid    = tid >> 5;
    const int lane   = tid & 31;
    const int g      = lane >> 2;
    const int tig    = lane & 3;
    const int warp_m = wid >> 2;
    const int warp_n = wid & 3;

    // stage B (weights) once, tf32-rounded
#pragma unroll
    for (int i = 0; i < 16; i++) {
        int idx = tid + i * 256;
        int r = idx >> 5, c4 = idx & 31;
        float4 v = ((const float4*)B)[idx];
        v.x = to_tf32(v.x); v.y = to_tf32(v.y); v.z = to_tf32(v.z); v.w = to_tf32(v.w);
        *(float4*)(B_s + r * SB + c4 * 4) = v;
    }

    uint32_t asA = (uint32_t)__cvta_generic_to_shared(sm);

    int t   = blockIdx.x;
    int buf = 0;
    if (STAGE == 1) {
        if (t < nTiles) {
            const int row0 = t * 128;
#pragma unroll
            for (int i = 0; i < 16; i++) {
                int idx = tid + i * 256;
                int r = idx >> 5, c4 = idx & 31;
                int gr = row0 + r;
                bool ok = gr < M;
                const float* gsrc = A + (size_t)(ok ? gr : 0) * 128 + c4 * 4;
                cp_async16(asA + (uint32_t)(r * SA + c4 * 4) * 4, gsrc, ok ? 16 : 0);
            }
        }
        CP_COMMIT();
    }

    for (; t < nTiles; t += gridDim.x) {
        const int row0 = t * 128;
        if (STAGE == 1) {
            const int tn = t + gridDim.x;
            if (tn < nTiles) {
                const int rowN = tn * 128;
                const uint32_t base = asA + (uint32_t)((buf ^ 1) * 128 * SA) * 4;
#pragma unroll
                for (int i = 0; i < 16; i++) {
                    int idx = tid + i * 256;
                    int r = idx >> 5, c4 = idx & 31;
                    int gr = rowN + r;
                    bool ok = gr < M;
                    const float* gsrc = A + (size_t)(ok ? gr : 0) * 128 + c4 * 4;
                    cp_async16(base + (uint32_t)(r * SA + c4 * 4) * 4, gsrc, ok ? 16 : 0);
                }
                CP_COMMIT();
                CP_WAIT(1);
            } else {
                CP_COMMIT();
                CP_WAIT(0);
            }
            __syncthreads();
        } else {
            __syncthreads();
#pragma unroll
            for (int i = 0; i < 16; i++) {
                int idx = tid + i * 256;
                int r = idx >> 5, c4 = idx & 31;
                int gr = row0 + r;
                float4 v = make_float4(0.f, 0.f, 0.f, 0.f);
                if (gr < M) v = *(const float4*)(A + (size_t)gr * 128 + c4 * 4);
                v.x = to_tf32(v.x); v.y = to_tf32(v.y); v.z = to_tf32(v.z); v.w = to_tf32(v.w);
                *(float4*)(sm + r * SA + c4 * 4) = v;
            }
            __syncthreads();
        }

        float acc[4][4][4];
#pragma unroll
        for (int mt = 0; mt < 4; mt++)
#pragma unroll
            for (int nt = 0; nt < 4; nt++)
#pragma unroll
                for (int q = 0; q < 4; q++) acc[mt][nt][q] = 0.f;

        const float* A_s = sm + buf * 128 * SA;
        const float* Ab = A_s + (warp_m * 64 + g) * SA + tig;
        const float* Bb = B_s + tig * SB + warp_n * 32 + g;
#pragma unroll
        for (int ks = 0; ks < 16; ks++) {
            const int kc = ks * 8;
            float af[4][4];
#pragma unroll
            for (int mt = 0; mt < 4; mt++) {
                const float* ap = Ab + mt * 16 * SA + kc;
                af[mt][0] = ap[0];
                af[mt][1] = ap[8 * SA];
                af[mt][2] = ap[4];
                af[mt][3] = ap[8 * SA + 4];
            }
            float bf[4][2];
#pragma unroll
            for (int nt = 0; nt < 4; nt++) {
                const float* bp = Bb + kc * SB + nt * 8;
                bf[nt][0] = bp[0];
                bf[nt][1] = bp[4 * SB];
            }
#pragma unroll
            for (int mt = 0; mt < 4; mt++)
#pragma unroll
                for (int nt = 0; nt < 4; nt++)
                    mma_tf32(acc[mt][nt][0], acc[mt][nt][1], acc[mt][nt][2], acc[mt][nt][3],
                             af[mt][0], af[mt][1], af[mt][2], af[mt][3],
                             bf[nt][0], bf[nt][1]);
        }

        // ---- epilogue ----
#pragma unroll
        for (int mt = 0; mt < 4; mt++) {
            int r0 = row0 + warp_m * 64 + mt * 16 + g;
            int r1 = r0 + 8;
            const float* e0 = nullptr; const float* e1 = nullptr;
            if (MODE != 0) {
                if (r0 < M) e0 = extra + (size_t)batch[r0] * 128;
                if (r1 < M) e1 = extra + (size_t)batch[r1] * 128;
            }
#pragma unroll
            for (int nt = 0; nt < 4; nt++) {
                int col = warp_n * 32 + nt * 8 + tig * 2;
                float o0 = acc[mt][nt][0], o1 = acc[mt][nt][1];
                float o2 = acc[mt][nt][2], o3 = acc[mt][nt][3];
                if (MODE == 1) {
                    if (e0) { o0 += e0[col]; o1 += e0[col + 1]; }
                    if (e1) { o2 += e1[col]; o3 += e1[col + 1]; }
                } else if (MODE == 2) {
                    float bc0 = bias[col], bc1 = bias[col + 1];
                    if (e0) { o0 = leaky(o0 + e0[col] + bc0); o1 = leaky(o1 + e0[col + 1] + bc1); }
                    if (e1) { o2 = leaky(o2 + e1[col] + bc0); o3 = leaky(o3 + e1[col + 1] + bc1); }
                }
                if (sizeof(OUT_T) == 2) {
                    __half2* Ch = (__half2*)C;
                    if (r0 < M) Ch[((size_t)r0 * 128 + col) >> 1] = __floats2half2_rn(o0, o1);
                    if (r1 < M) Ch[((size_t)r1 * 128 + col) >> 1] = __floats2half2_rn(o2, o3);
                } else {
                    float* Cf = (float*)C;
                    if (r0 < M) *(float2*)(Cf + (size_t)r0 * 128 + col) = make_float2(o0, o1);
                    if (r1 < M) *(float2*)(Cf + (size_t)r1 * 128 + col) = make_float2(o2, o3);
                }
            }
        }
        if (STAGE == 1) buf ^= 1;   // FIX: STAGE 0 has a single A buffer; never toggle
        __syncthreads();
    }
}

// ---------------- aggregation (fp16 gather): one warp per dst node -------------
// out[i] = to_tf32( leaky( sum_e w_e * xw[src_e] + bias ) )
__global__ void k_agg_h(const __half* __restrict__ xw, float* __restrict__ out,
                        const float* __restrict__ bias, int n) {
    int gw   = (blockIdx.x * blockDim.x + threadIdx.x) >> 5;
    int lane = threadIdx.x & 31;
    if (gw >= n) return;
    int s = g_row_start[gw];
    int e = g_row_start[gw + 1];
    float4 acc0 = make_float4(0.f, 0.f, 0.f, 0.f);
    float4 acc1 = make_float4(0.f, 0.f, 0.f, 0.f);
    int i = s;
    for (; i + 1 < e; i += 2) {
        int2 e0 = g_perm[i];
        int2 e1 = g_perm[i + 1];
        float w0 = __int_as_float(e0.y);
        float w1 = __int_as_float(e1.y);
        uint2 u0 = *(const uint2*)((const __half2*)(xw + (size_t)e0.x * D) + lane * 2);
        uint2 u1 = *(const uint2*)((const __half2*)(xw + (size_t)e1.x * D) + lane * 2);
        float2 a = __half22float2(*(__half2*)&u0.x);
        float2 b = __half22float2(*(__half2*)&u0.y);
        float2 c = __half22float2(*(__half2*)&u1.x);
        float2 d = __half22float2(*(__half2*)&u1.y);
        acc0.x = fmaf(w0, a.x, acc0.x); acc0.y = fmaf(w0, a.y, acc0.y);
        acc0.z = fmaf(w0, b.x, acc0.z); acc0.w = fmaf(w0, b.y, acc0.w);
        acc1.x = fmaf(w1, c.x, acc1.x); acc1.y = fmaf(w1, c.y, acc1.y);
        acc1.z = fmaf(w1, d.x, acc1.z); acc1.w = fmaf(w1, d.y, acc1.w);
    }
    if (i < e) {
        int2 e0 = g_perm[i];
        float w0 = __int_as_float(e0.y);
        uint2 u0 = *(const uint2*)((const __half2*)(xw + (size_t)e0.x * D) + lane * 2);
        float2 a = __half22float2(*(__half2*)&u0.x);
        float2 b = __half22float2(*(__half2*)&u0.y);
        acc0.x = fmaf(w0, a.x, acc0.x); acc0.y = fmaf(w0, a.y, acc0.y);
        acc0.z = fmaf(w0, b.x, acc0.z); acc0.w = fmaf(w0, b.y, acc0.w);
    }
    float4 bv = *(const float4*)(bias + lane * 4);
    float4 acc = make_float4(to_tf32(leaky(acc0.x + acc1.x + bv.x)),
                             to_tf32(leaky(acc0.y + acc1.y + bv.y)),
                             to_tf32(leaky(acc0.z + acc1.z + bv.z)),
                             to_tf32(leaky(acc0.w + acc1.w + bv.w)));
    *(float4*)(out + (size_t)gw * D + lane * 4) = acc;
}

// ---------------- launch ------------------------------------------------------
extern "C" void kernel_launch(void* const* d_in, const int* in_sizes, int n_in,
                              void* d_out, int out_size) {
    const float* features = (const float*)d_in[0];
    const float* values   = (const float*)d_in[1];
    const float* W1       = (const float*)d_in[2];
    const float* b1       = (const float*)d_in[3];
    const float* W2       = (const float*)d_in[4];
    const float* b2       = (const float*)d_in[5];
    const float* Wl       = (const float*)d_in[6];
    const float* bl       = (const float*)d_in[7];
    const int*   adjs     = (const int*)d_in[8];
    const int*   root_idx = (const int*)d_in[9];
    const int*   batch    = (const int*)d_in[12];
    float*       out      = (float*)d_out;

    const int N = in_sizes[0] / D;
    const int E = in_sizes[1];
    const int B = in_sizes[9];
    const int* src = adjs;
    const int* dst = adjs + E;

    __half *p_xh1, *p_xh2;
    float  *p_lh1, *p_la2, *p_r2, *p_r3;
    int    *p_cnt;
    cudaGetSymbolAddress((void**)&p_xh1, g_xh1);
    cudaGetSymbolAddress((void**)&p_xh2, g_xh2);
    cudaGetSymbolAddress((void**)&p_lh1, g_lh1);
    cudaGetSymbolAddress((void**)&p_la2, g_la2);
    cudaGetSymbolAddress((void**)&p_r2, g_r2);
    cudaGetSymbolAddress((void**)&p_r3, g_r3);
    cudaGetSymbolAddress((void**)&p_cnt, g_cnt);

    static cudaStream_t s_side = nullptr;
    static cudaEvent_t  ev_fork = nullptr, ev_join = nullptr, ev_h1 = nullptr, ev_r3 = nullptr;
    if (s_side == nullptr) {
        cudaStreamCreateWithFlags(&s_side, cudaStreamNonBlocking);
        cudaEventCreateWithFlags(&ev_fork, cudaEventDisableTiming);
        cudaEventCreateWithFlags(&ev_join, cudaEventDisableTiming);
        cudaEventCreateWithFlags(&ev_h1,   cudaEventDisableTiming);
        cudaEventCreateWithFlags(&ev_r3,   cudaEventDisableTiming);
        cudaFuncSetAttribute(k_scan2, cudaFuncAttributeMaxDynamicSharedMemorySize, 220 * 1024);
        cudaFuncSetAttribute(k_mma<0, 0, __half>, cudaFuncAttributeMaxDynamicSharedMemorySize, 140 * 1024);
        cudaFuncSetAttribute(k_mma<1, 1, __half>, cudaFuncAttributeMaxDynamicSharedMemorySize, 210 * 1024);
        cudaFuncSetAttribute(k_mma<2, 1, float>,  cudaFuncAttributeMaxDynamicSharedMemorySize, 210 * 1024);
    }

    const size_t scan_smem  = (size_t)(N + 1) * sizeof(int);
    const size_t mma_smem0  = (size_t)(128 * SA + 128 * SB) * sizeof(float);       // 1 A buf
    const size_t mma_smem1  = (size_t)(2 * 128 * SA + 128 * SB) * sizeof(float);   // 2 A bufs
    const int nTiles    = (N + 127) / 128;
    const int mmaGrid   = nTiles < 148 ? nTiles : 148;
    const int aggBlocks = (N * 32 + 255) / 256;

    // ---- fork: CSR on side stream, overlapped with GEMM1 + r2 ----
    cudaEventRecord(ev_fork, 0);
    cudaStreamWaitEvent(s_side, ev_fork, 0);
    cudaMemsetAsync(p_cnt, 0, (size_t)N * sizeof(int), s_side);
    k_hist<<<(E + 255) / 256, 256, 0, s_side>>>(dst, E);
    k_scan2<<<1, 1024, scan_smem, s_side>>>(N);
    k_scatter<<<(E + 255) / 256, 256, 0, s_side>>>(src, dst, values, E);
    cudaEventRecord(ev_join, s_side);

    // main: GEMM1 (xh1 = features @ W1, fp16 out) then r2
    k_mma<0, 0, __half><<<mmaGrid, 256, mma_smem0>>>(features, W1, p_xh1, N,
                                                     nullptr, nullptr, nullptr, nTiles);
    k_rootp2<<<B, 512>>>(features, W2, p_r2, root_idx, 0);

    cudaStreamWaitEvent(0, ev_join, 0);

    // agg1: lh1 = tf32(leaky(agg(xh1) + b1))
    k_agg_h<<<aggBlocks, 256>>>(p_xh1, p_lh1, b1, N);

    // r3 = inv_leaky(lh1[root]) @ Wl_bot on side stream (hidden under GEMM2/agg2)
    cudaEventRecord(ev_h1, 0);
    cudaStreamWaitEvent(s_side, ev_h1, 0);
    k_rootp2<<<B, 512, 0, s_side>>>(p_lh1, Wl, p_r3, root_idx, 1);
    cudaEventRecord(ev_r3, s_side);

    // GEMM2: xh2 = lh1 @ W2_top + r2[batch]  (fp16 out, cp.async path)
    k_mma<1, 1, __half><<<mmaGrid, 256, mma_smem1>>>(p_lh1, W2, p_xh2, N,
                                                     p_r2, batch, nullptr, nTiles);
    // agg2: la2 = tf32(leaky(agg(xh2) + b2))
    k_agg_h<<<aggBlocks, 256>>>(p_xh2, p_la2, b2, N);

    cudaStreamWaitEvent(0, ev_r3, 0);
    // GEMM3: out = leaky(la2 @ Wl_top + r3[batch] + bl)
    k_mma<2, 1, float><<<mmaGrid, 256, mma_smem1>>>(p_la2, Wl, out, N,
                                                    p_r3, batch, bl, nTiles);
}